// round 4
// baseline (speedup 1.0000x reference)
#include <cuda_runtime.h>
#include <cstdint>

typedef unsigned long long u64;

#define NPIX 32768
#define NBLK 1024

// ---------------- scratch ----------------
__device__ float g_bufA[NPIX*324];
__device__ float g_bufB[NPIX*324];
__device__ float g_bufC[NPIX*324];
__device__ float g_bufD[NPIX*324];
__device__ float g_bufE[NPIX*324];
__device__ float g_bufF[NPIX*720];   // duplicated-pair activated buffer

__device__ float g_psum[NBLK*324];
__device__ float g_psq [NBLK*324];
__device__ float g_scale[12][324];
__device__ float g_shift[12][324];

// ---------------- f32x2 helpers ----------------
__device__ __forceinline__ u64 pk2(float lo, float hi){ u64 r; asm("mov.b64 %0,{%1,%2};":"=l"(r):"f"(lo),"f"(hi)); return r; }
__device__ __forceinline__ u64 dup2(float v){ return pk2(v, v); }
__device__ __forceinline__ void fma2(u64 &d, u64 a, u64 b){ asm("fma.rn.f32x2 %0,%1,%2,%0;":"+l"(d):"l"(a),"l"(b)); }

// acc[0..8] += xd * row[0..8]   (row = 18 floats as 9 f32x2, 16B-aligned)
#define FMA9(acc, xd, vbase) { \
  const ulonglong2* _vv = (const ulonglong2*)(vbase); \
  ulonglong2 _a0=_vv[0], _a1=_vv[1], _a2=_vv[2], _a3=_vv[3]; \
  u64 _a8 = ((const u64*)(vbase))[8]; \
  fma2(acc[0],xd,_a0.x); fma2(acc[1],xd,_a0.y); \
  fma2(acc[2],xd,_a1.x); fma2(acc[3],xd,_a1.y); \
  fma2(acc[4],xd,_a2.x); fma2(acc[5],xd,_a2.y); \
  fma2(acc[6],xd,_a3.x); fma2(acc[7],xd,_a3.y); \
  fma2(acc[8],xd,_a8); }

#define ST9(dst, acc) { \
  ulonglong2* _dd=(ulonglong2*)(dst); \
  _dd[0]=make_ulonglong2(acc[0],acc[1]); _dd[1]=make_ulonglong2(acc[2],acc[3]); \
  _dd[2]=make_ulonglong2(acc[4],acc[5]); _dd[3]=make_ulonglong2(acc[6],acc[7]); \
  ((u64*)(dst))[8]=acc[8]; }

#define LD9BIAS(yacc, bptr) { \
  const ulonglong2* _bb = (const ulonglong2*)(bptr); \
  ulonglong2 _b0=_bb[0], _b1=_bb[1], _b2=_bb[2], _b3=_bb[3]; \
  yacc[0]=_b0.x; yacc[1]=_b0.y; yacc[2]=_b1.x; yacc[3]=_b1.y; \
  yacc[4]=_b2.x; yacc[5]=_b2.y; yacc[6]=_b3.x; yacc[7]=_b3.y; \
  yacc[8]=((const u64*)(bptr))[8]; }

// ---------------- f0 ----------------
// 576 threads = 32 pixels x 18. grid (32 h, 32 b).
__global__ void __launch_bounds__(576) f0_kernel(const float* __restrict__ x,
    const float* __restrict__ U0, const float* __restrict__ V0,
    const float* __restrict__ b0, float* __restrict__ out)
{
    extern __shared__ float sm[];
    float* sT   = sm;                 // 25344
    float* sUt2 = sm + 25344;         // 5184  dup pairs [tap][p*18+a]*2
    float* sVp  = sm + 30528;         // 2880  [tap][qq*20+d]
    float* sN   = sm + 33408;         // 11520 [pixl][row*20+d]
    const int t = threadIdx.x;
    const int j = t % 18, pixl = t / 18;
    const int h = blockIdx.x, b = blockIdx.y;

    u64 yacc[9];
    #pragma unroll
    for (int k = 0; k < 9; ++k) yacc[k] = *(const u64*)(b0 + j*18 + 2*k);

    for (int c = 0; c < 8; ++c) {
        __syncthreads();
        const float* xc = x + (size_t)(b*8 + c)*262144;
        for (int e = t; e < 24576; e += 576) {
            int rr = e >> 13, rem = e & 8191;
            int pq = rem >> 5, w = rem & 31;
            int hr = h - 1 + rr;
            int p = pq >> 4, qq = pq & 15;
            sT[rr*8448 + (qq*16 + p)*33 + w] = ((unsigned)hr < 32u) ? xc[pq*1024 + hr*32 + w] : 0.f;
        }
        const float* U0c = U0 + c*2592;   // [tap][a][p]
        const float* V0c = V0 + c*2592;   // [tap][qq][d]
        for (int e = t; e < 2592; e += 576) {
            int tap = e/288, r = e%288, a = r/16, p = r%16;
            float v = U0c[e];
            int o = (tap*288 + p*18 + a)*2;
            sUt2[o] = v; sUt2[o+1] = v;
        }
        for (int e = t; e < 2880; e += 576) {
            int tap = e/320, r = e%320, qq = r/20, d = r%20;
            sVp[e] = (d < 18) ? V0c[(tap*16 + qq)*18 + d] : 0.f;
        }
        __syncthreads();

        for (int tap = 0; tap < 9; ++tap) {
            const int di = tap/3, dj = tap%3;
            const int iw = pixl + dj - 1;
            const bool valid = (unsigned)iw < 32u;
            if (valid && j < 16) {
                const float* Tb = sT + di*8448 + iw;
                u64 nacc[9];
                #pragma unroll
                for (int k = 0; k < 9; ++k) nacc[k] = 0ull;
                #pragma unroll
                for (int qq = 0; qq < 16; ++qq) {
                    u64 xd = dup2(Tb[(qq*16 + j)*33]);
                    FMA9(nacc, xd, sVp + tap*320 + qq*20);
                }
                ST9(sN + pixl*360 + j*20, nacc);
            }
            __syncthreads();
            if (valid) {
                #pragma unroll
                for (int p = 0; p < 16; ++p) {
                    u64 ud = *(const u64*)(sUt2 + (tap*288 + p*18 + j)*2);
                    FMA9(yacc, ud, sN + pixl*360 + p*20);
                }
            }
            __syncthreads();
        }
    }
    const int bid = b*32 + h;
    const size_t obase = ((size_t)bid*32 + pixl)*324 + j*18;
    #pragma unroll
    for (int k = 0; k < 9; ++k) *(u64*)(out + obase + 2*k) = yacc[k];
    ST9(sN + pixl*360 + j*20, yacc);
    __syncthreads();
    if (t < 324) {
        int a = t/18, d = t - a*18;
        float s = 0.f, ss = 0.f;
        #pragma unroll 4
        for (int pp = 0; pp < 32; ++pp) {
            float v = sN[pp*360 + a*20 + d];
            s += v; ss = fmaf(v, v, ss);
        }
        g_psum[bid*324 + t] = s;
        g_psq [bid*324 + t] = ss;
    }
}

// ---------------- activation: BN + PReLU, duplicated-pair output ----------------
// out[pix][j][4q..4q+3] = (v0,v0,v1,v1); row pitch 40 floats.
__global__ void __launch_bounds__(576) act_kernel(
    const float* __restrict__ in, int slot, const float* __restrict__ alpha_ptr,
    float* __restrict__ outd)
{
    __shared__ float sSc[324], sSh[324];
    const int t = threadIdx.x;
    const int j = t % 18, pixl = t / 18;
    for (int e = t; e < 324; e += 576) { sSc[e] = g_scale[slot][e]; sSh[e] = g_shift[slot][e]; }
    const float alpha = *alpha_ptr;
    __syncthreads();
    const int pix = blockIdx.x*32 + pixl;
    const float* ip = in + (size_t)pix*324 + j*18;
    float* op = outd + (size_t)pix*720 + j*40;
    #pragma unroll
    for (int q = 0; q < 9; ++q) {
        float2 v  = *(const float2*)(ip + 2*q);
        float2 sc = *(const float2*)(sSc + j*18 + 2*q);
        float2 sh = *(const float2*)(sSh + j*18 + 2*q);
        float a0 = fmaf(v.x, sc.x, sh.x); if (a0 < 0.f) a0 *= alpha;
        float a1 = fmaf(v.y, sc.y, sh.y); if (a1 < 0.f) a1 *= alpha;
        *(float4*)(op + 4*q) = make_float4(a0, a0, a1, a1);
    }
}

// ---------------- conv1x1 (single w/ BN+PReLU, or dual fused-combine) ----------------
__global__ void __launch_bounds__(576) conv1x1_kernel(
    const float* __restrict__ in, int slot, const float* __restrict__ alpha_ptr,
    const float* __restrict__ inB, int slotB,
    const float* __restrict__ U, const float* __restrict__ V,
    const float* __restrict__ bm, float* __restrict__ out)
{
    extern __shared__ float sm[];
    float* sV   = sm;           // 360  [q*20+d]
    float* sUt2 = sm + 360;     // 648  dup pairs [p*18+a]*2
    float* sBp  = sm + 1008;    // 360
    float* sScA = sm + 1368;    // 324
    float* sShA = sm + 1692;    // 324
    float* sScB = sm + 2016;    // 324
    float* sShB = sm + 2340;    // 324
    float* sN   = sm + 2664;    // 11520
    const int t = threadIdx.x;
    const int j = t % 18, pixl = t / 18;

    if (t < 360) { int q = t/20, d = t%20;
        sV[t]  = (d < 18) ? V[q*18 + d]  : 0.f;
        sBp[t] = (d < 18) ? bm[q*18 + d] : 0.f; }
    for (int e = t; e < 324; e += 576) {
        float u = U[e];
        int o = ((e%18)*18 + e/18)*2;
        sUt2[o] = u; sUt2[o+1] = u;
        sScA[e] = g_scale[slot][e];
        sShA[e] = g_shift[slot][e];
        if (inB) { sScB[e] = g_scale[slotB][e]; sShB[e] = g_shift[slotB][e]; }
    }
    const float alpha = alpha_ptr ? *alpha_ptr : 1.f;
    __syncthreads();

    const size_t base = ((size_t)blockIdx.x*32 + pixl)*324 + j*18;
    float xr[18];
    if (inB) {
        #pragma unroll
        for (int q = 0; q < 9; ++q) {
            float2 va = *(const float2*)(in  + base + 2*q);
            float2 vb = *(const float2*)(inB + base + 2*q);
            float2 scA = *(const float2*)(sScA + j*18 + 2*q);
            float2 shA = *(const float2*)(sShA + j*18 + 2*q);
            float2 scB = *(const float2*)(sScB + j*18 + 2*q);
            float2 shB = *(const float2*)(sShB + j*18 + 2*q);
            xr[2*q]   = fmaf(va.x, scA.x, shA.x) + fmaf(vb.x, scB.x, shB.x);
            xr[2*q+1] = fmaf(va.y, scA.y, shA.y) + fmaf(vb.y, scB.y, shB.y);
        }
    } else {
        #pragma unroll
        for (int q = 0; q < 9; ++q) {
            float2 v  = *(const float2*)(in + base + 2*q);
            float2 sc = *(const float2*)(sScA + j*18 + 2*q);
            float2 sh = *(const float2*)(sShA + j*18 + 2*q);
            float a0 = fmaf(v.x, sc.x, sh.x); if (a0 < 0.f) a0 *= alpha;
            float a1 = fmaf(v.y, sc.y, sh.y); if (a1 < 0.f) a1 *= alpha;
            xr[2*q] = a0; xr[2*q+1] = a1;
        }
    }
    u64 nacc[9];
    #pragma unroll
    for (int k = 0; k < 9; ++k) nacc[k] = 0ull;
    #pragma unroll
    for (int q = 0; q < 18; ++q) {
        u64 xd = dup2(xr[q]);
        FMA9(nacc, xd, sV + q*20);
    }
    ST9(sN + pixl*360 + j*20, nacc);
    __syncthreads();

    u64 yacc[9];
    LD9BIAS(yacc, sBp + j*20);
    #pragma unroll
    for (int p = 0; p < 18; ++p) {
        u64 ud = *(const u64*)(sUt2 + (p*18 + j)*2);
        FMA9(yacc, ud, sN + pixl*360 + p*20);
    }
    #pragma unroll
    for (int k = 0; k < 9; ++k) *(u64*)(out + base + 2*k) = yacc[k];
    __syncthreads();
    ST9(sN + pixl*360 + j*20, yacc);
    __syncthreads();
    if (t < 324) {
        int a = t/18, d = t - a*18;
        float s = 0.f, ss = 0.f;
        #pragma unroll 4
        for (int pp = 0; pp < 32; ++pp) {
            float v = sN[pp*360 + a*20 + d];
            s += v; ss = fmaf(v, v, ss);
        }
        g_psum[blockIdx.x*324 + t] = s;
        g_psq [blockIdx.x*324 + t] = ss;
    }
}

// ---------------- conv3x3 (reads pre-activated duplicated-pair buffer) ----------------
__global__ void __launch_bounds__(576) conv3x3_kernel(
    const float* __restrict__ actd,
    const float* __restrict__ U9, const float* __restrict__ V9,
    const float* __restrict__ bm, float* __restrict__ out)
{
    extern __shared__ float sm[];
    float* sV   = sm;            // 3240 [tap][q*20+d]
    float* sUt2 = sm + 3240;     // 5832 dup pairs [tap][p*18+a]*2
    float* sBp  = sm + 9072;     // 360
    float* sN   = sm + 9432;     // 11520
    const int t = threadIdx.x;
    const int j = t % 18, pixl = t / 18;

    for (int e = t; e < 3240; e += 576) {
        int tap = e/360, r = e%360, q = r/20, d = r%20;
        sV[e] = (d < 18) ? V9[(tap*18 + q)*18 + d] : 0.f;
    }
    for (int e = t; e < 2916; e += 576) {
        int tap = e/324, r = e%324, a = r/18, p = r%18;
        float u = U9[e];
        int o = (tap*324 + p*18 + a)*2;
        sUt2[o] = u; sUt2[o+1] = u;
    }
    if (t < 360) { int q = t/20, d = t%20; sBp[t] = (d < 18) ? bm[q*18 + d] : 0.f; }
    __syncthreads();

    const int pix = blockIdx.x*32 + pixl;
    const int hw = pix & 1023, hh = hw >> 5, ww = hw & 31;
    u64 yacc[9];
    LD9BIAS(yacc, sBp + j*20);

    for (int tap = 0; tap < 9; ++tap) {
        const int di = tap/3 - 1, dj = tap%3 - 1;
        const bool valid = ((unsigned)(hh + di) < 32u) && ((unsigned)(ww + dj) < 32u);
        if (valid) {
            const u64* xd = (const u64*)(actd + ((size_t)pix + di*32 + dj)*720 + j*40);
            u64 nacc[9];
            #pragma unroll
            for (int k = 0; k < 9; ++k) nacc[k] = 0ull;
            #pragma unroll
            for (int q = 0; q < 18; ++q) {
                FMA9(nacc, xd[q], sV + tap*360 + q*20);
            }
            ST9(sN + pixl*360 + j*20, nacc);
        }
        __syncthreads();
        if (valid) {
            #pragma unroll
            for (int p = 0; p < 18; ++p) {
                u64 ud = *(const u64*)(sUt2 + (tap*324 + p*18 + j)*2);
                FMA9(yacc, ud, sN + pixl*360 + p*20);
            }
        }
        __syncthreads();
    }
    const size_t base = (size_t)pix*324 + j*18;
    #pragma unroll
    for (int k = 0; k < 9; ++k) *(u64*)(out + base + 2*k) = yacc[k];
    ST9(sN + pixl*360 + j*20, yacc);
    __syncthreads();
    if (t < 324) {
        int a = t/18, d = t - a*18;
        float s = 0.f, ss = 0.f;
        #pragma unroll 4
        for (int pp = 0; pp < 32; ++pp) {
            float v = sN[pp*360 + a*20 + d];
            s += v; ss = fmaf(v, v, ss);
        }
        g_psum[blockIdx.x*324 + t] = s;
        g_psq [blockIdx.x*324 + t] = ss;
    }
}

// ---------------- finalize: float4 coalesced-ish reduce ----------------
// grid 81 blocks x 128 threads; block handles 4 inner positions.
__global__ void __launch_bounds__(128) finalize_kernel(
    const float* __restrict__ gamma, const float* __restrict__ beta, int slot)
{
    __shared__ float red[8][128];
    const int t = threadIdx.x;
    const int bp = blockIdx.x * 4;
    float s0=0,s1=0,s2=0,s3=0,q0=0,q1=0,q2=0,q3=0;
    for (int i = t; i < NBLK; i += 128) {
        float4 a = *(const float4*)(g_psum + i*324 + bp);
        float4 b = *(const float4*)(g_psq  + i*324 + bp);
        s0+=a.x; s1+=a.y; s2+=a.z; s3+=a.w;
        q0+=b.x; q1+=b.y; q2+=b.z; q3+=b.w;
    }
    red[0][t]=s0; red[1][t]=s1; red[2][t]=s2; red[3][t]=s3;
    red[4][t]=q0; red[5][t]=q1; red[6][t]=q2; red[7][t]=q3;
    __syncthreads();
    for (int k = 64; k > 0; k >>= 1) {
        if (t < k) {
            #pragma unroll
            for (int c = 0; c < 8; ++c) red[c][t] += red[c][t+k];
        }
        __syncthreads();
    }
    if (t < 4) {
        const int pos = bp + t;
        float mean = red[t][0] * (1.f/32768.f);
        float var  = red[4+t][0] * (1.f/32768.f) - mean*mean;
        float inv  = rsqrtf(var + 1e-5f);
        float sc   = gamma[pos]*inv;
        g_scale[slot][pos] = sc;
        g_shift[slot][pos] = beta[pos] - mean*sc;
    }
}

// ---------------- head ----------------
__global__ void __launch_bounds__(324) head_kernel(
    const float* __restrict__ a, int slotA,
    const float* __restrict__ b, int slotB,
    const float* __restrict__ Wf, const float* __restrict__ bf,
    float* __restrict__ out) {
    __shared__ float sW[3240], sX[324], sPart[180];
    const int t = threadIdx.x;
    for (int e = t; e < 3240; e += 324) sW[e] = Wf[e];
    const float sA = g_scale[slotA][t], hA = g_shift[slotA][t];
    const float sB = g_scale[slotB][t], hB = g_shift[slotB][t];
    __syncthreads();
    const int pix0 = blockIdx.x * 8;
    for (int k = 0; k < 8; ++k) {
        const int pix = pix0 + k;
        const size_t base = (size_t)pix * 324;
        sX[t] = fmaf(a[base+t], sA, hA) + fmaf(b[base+t], sB, hB);
        __syncthreads();
        if (t < 180) {
            const int o = t/18, p = t - o*18;
            const float* xr = sX + p*18;
            const float* wr = sW + o*324 + p*18;
            float s = 0.f;
            #pragma unroll
            for (int q = 0; q < 18; ++q) s = fmaf(xr[q], wr[q], s);
            sPart[t] = s;
        }
        __syncthreads();
        if (t < 10) {
            float r = bf[t];
            #pragma unroll
            for (int p = 0; p < 18; ++p) r += sPart[t*18 + p];
            const int bb = pix >> 10, hw = pix & 1023;
            out[(size_t)(bb*10 + t)*1024 + hw] = r;
        }
        __syncthreads();
    }
}

// ---------------- host ----------------
extern "C" void kernel_launch(void* const* d_in, const int* in_sizes, int n_in,
                              void* d_out, int out_size) {
    (void)in_sizes; (void)n_in; (void)out_size;
    const float* x     = (const float*)d_in[0];
    const float* U0    = (const float*)d_in[1];
    const float* V0    = (const float*)d_in[2];
    const float* b0    = (const float*)d_in[3];
    const float* U1    = (const float*)d_in[4];
    const float* V1    = (const float*)d_in[5];
    const float* b1    = (const float*)d_in[6];
    const float* U3    = (const float*)d_in[7];
    const float* V3    = (const float*)d_in[8];
    const float* b3    = (const float*)d_in[9];
    const float* Wf    = (const float*)d_in[10];
    const float* bf    = (const float*)d_in[11];
    const float* gamma = (const float*)d_in[12];
    const float* beta  = (const float*)d_in[13];
    const float* alpha = (const float*)d_in[14];
    float* out = (float*)d_out;

    float *bufA, *bufB, *bufC, *bufD, *bufE, *bufF;
    cudaGetSymbolAddress((void**)&bufA, g_bufA);
    cudaGetSymbolAddress((void**)&bufB, g_bufB);
    cudaGetSymbolAddress((void**)&bufC, g_bufC);
    cudaGetSymbolAddress((void**)&bufD, g_bufD);
    cudaGetSymbolAddress((void**)&bufE, g_bufE);
    cudaGetSymbolAddress((void**)&bufF, g_bufF);

    const int F0_SMEM = 44928 * 4;
    const int C1_SMEM = 14184 * 4;
    const int C3_SMEM = 20952 * 4;
    cudaFuncSetAttribute(f0_kernel,      cudaFuncAttributeMaxDynamicSharedMemorySize, F0_SMEM);
    cudaFuncSetAttribute(conv1x1_kernel, cudaFuncAttributeMaxDynamicSharedMemorySize, C1_SMEM);
    cudaFuncSetAttribute(conv3x3_kernel, cudaFuncAttributeMaxDynamicSharedMemorySize, C3_SMEM);

    #define FIN(slot, grow) finalize_kernel<<<81,128>>>(gamma + (grow)*324, beta + (grow)*324, (slot))
    #define C1S(in, slot, al, wi, dst) \
        conv1x1_kernel<<<1024,576,C1_SMEM>>>((in), (slot), (al), nullptr, 0, U1+(wi)*324, V1+(wi)*324, b1+(wi)*324, (dst))
    #define C1D(inA, sA, inB, sB, wi, dst) \
        conv1x1_kernel<<<1024,576,C1_SMEM>>>((inA), (sA), nullptr, (inB), (sB), U1+(wi)*324, V1+(wi)*324, b1+(wi)*324, (dst))

    // f0 -> A (raw h)
    f0_kernel<<<dim3(32,32), 576, F0_SMEM>>>(x, U0, V0, b0, bufA);
    FIN(0, 0);

    // ---- block 1 ----
    C1S(bufA, 0, alpha+0, 0, bufB);   FIN(1, 1);      // s1 raw
    C1S(bufA, 0, alpha+0, 1, bufD);   FIN(2, 2);      // t1 raw
    act_kernel<<<1024,576>>>(bufD, 2, alpha+1, bufF);
    conv3x3_kernel<<<1024,576,C3_SMEM>>>(bufF, U3+0*2916, V3+0*2916, b3+0*324, bufE);
    FIN(3, 3);                                         // t2 raw
    C1S(bufE, 3, alpha+2, 2, bufD);   FIN(4, 4);      // t3 raw (block1)

    // ---- block 2 (input x11 = bn(D,4)+bn(B,1), fused) ----
    C1D(bufD, 4, bufB, 1, 3, bufC);   FIN(5, 5);      // s2 raw (kept for block 3)
    C1D(bufD, 4, bufB, 1, 4, bufA);   FIN(6, 6);      // t1 raw
    act_kernel<<<1024,576>>>(bufA, 6, alpha+3, bufF);
    conv3x3_kernel<<<1024,576,C3_SMEM>>>(bufF, U3+1*2916, V3+1*2916, b3+1*324, bufE);
    FIN(7, 7);                                         // t2 raw
    C1S(bufE, 7, alpha+4, 5, bufD);   FIN(8, 8);      // t3 raw (block2)

    // ---- block 3 (input x21 = bn(D,8)+bn(C,5); bug-faithful identity = bn(s2)) ----
    C1D(bufD, 8, bufC, 5, 7, bufA);   FIN(9, 10);     // t1 raw
    act_kernel<<<1024,576>>>(bufA, 9, alpha+5, bufF);
    conv3x3_kernel<<<1024,576,C3_SMEM>>>(bufF, U3+2*2916, V3+2*2916, b3+2*324, bufE);
    FIN(10, 11);                                       // t2 raw
    C1S(bufE, 10, alpha+6, 8, bufD);  FIN(11, 12);    // t3 raw (block3)

    // head: out = <bn(t3,11) + bn(s2,5), Wf> + bf
    head_kernel<<<4096,324>>>(bufD, 11, bufC, 5, Wf, bf, out);
}

// round 5
// speedup vs baseline: 1.1555x; 1.1555x over previous
#include <cuda_runtime.h>
#include <cstdint>

typedef unsigned long long u64;

#define NPIX 32768
#define NBLK 1024

// ---------------- scratch ----------------
__device__ float g_bufA[NPIX*324];
__device__ float g_bufB[NPIX*324];
__device__ float g_bufC[NPIX*324];
__device__ float g_bufD[NPIX*324];
__device__ float g_bufE[NPIX*324];

__device__ float g_psum0[NBLK*324];
__device__ float g_psq0 [NBLK*324];
__device__ float g_psum1[NBLK*324];
__device__ float g_psq1 [NBLK*324];
__device__ float g_scale[12][324];
__device__ float g_shift[12][324];

// ---------------- f32x2 helpers ----------------
__device__ __forceinline__ u64 pk2(float lo, float hi){ u64 r; asm("mov.b64 %0,{%1,%2};":"=l"(r):"f"(lo),"f"(hi)); return r; }
__device__ __forceinline__ u64 dup2(float v){ return pk2(v, v); }
__device__ __forceinline__ void fma2(u64 &d, u64 a, u64 b){ asm("fma.rn.f32x2 %0,%1,%2,%0;":"+l"(d):"l"(a),"l"(b)); }

#define FMA9(acc, xd, vbase) { \
  const ulonglong2* _vv = (const ulonglong2*)(vbase); \
  ulonglong2 _a0=_vv[0], _a1=_vv[1], _a2=_vv[2], _a3=_vv[3]; \
  u64 _a8 = ((const u64*)(vbase))[8]; \
  fma2(acc[0],xd,_a0.x); fma2(acc[1],xd,_a0.y); \
  fma2(acc[2],xd,_a1.x); fma2(acc[3],xd,_a1.y); \
  fma2(acc[4],xd,_a2.x); fma2(acc[5],xd,_a2.y); \
  fma2(acc[6],xd,_a3.x); fma2(acc[7],xd,_a3.y); \
  fma2(acc[8],xd,_a8); }

#define ST9(dst, acc) { \
  ulonglong2* _dd=(ulonglong2*)(dst); \
  _dd[0]=make_ulonglong2(acc[0],acc[1]); _dd[1]=make_ulonglong2(acc[2],acc[3]); \
  _dd[2]=make_ulonglong2(acc[4],acc[5]); _dd[3]=make_ulonglong2(acc[6],acc[7]); \
  ((u64*)(dst))[8]=acc[8]; }

#define LD9BIAS(yacc, bptr) { \
  const ulonglong2* _bb = (const ulonglong2*)(bptr); \
  ulonglong2 _b0=_bb[0], _b1=_bb[1], _b2=_bb[2], _b3=_bb[3]; \
  yacc[0]=_b0.x; yacc[1]=_b0.y; yacc[2]=_b1.x; yacc[3]=_b1.y; \
  yacc[4]=_b2.x; yacc[5]=_b2.y; yacc[6]=_b3.x; yacc[7]=_b3.y; \
  yacc[8]=((const u64*)(bptr))[8]; }

// ---------------- f0 ----------------
// 576 threads = 32 pixels x 18. grid (32 h, 32 b). One di-row of T staged at a time.
// smem: sT1[256*33]=8448, sUt2[9*288*2]=5184, sVp[9*320]=2880, sN[32*360]=11520 -> 28032 w = 112128 B
__global__ void __launch_bounds__(576,2) f0_kernel(const float* __restrict__ x,
    const float* __restrict__ U0, const float* __restrict__ V0,
    const float* __restrict__ b0, float* __restrict__ out)
{
    extern __shared__ float sm[];
    float* sT1  = sm;             // 8448
    float* sUt2 = sm + 8448;      // 5184 dup pairs [tap][(p*18+a)*2]
    float* sVp  = sm + 13632;     // 2880 [tap][qq*20+d]
    float* sN   = sm + 16512;     // 11520
    const int t = threadIdx.x;
    const int j = t % 18, pixl = t / 18;
    const int h = blockIdx.x, b = blockIdx.y;

    u64 yacc[9];
    #pragma unroll
    for (int k = 0; k < 9; ++k) yacc[k] = *(const u64*)(b0 + j*18 + 2*k);

    for (int c = 0; c < 8; ++c) {
        const float* xc  = x  + (size_t)(b*8 + c)*262144;
        const float* U0c = U0 + c*2592;   // [tap][a][p]
        const float* V0c = V0 + c*2592;   // [tap][qq][d]
        // weights (protected by trailing sync of previous tap / first iteration trivially safe)
        for (int e = t; e < 2592; e += 576) {
            int tap = e/288, r = e%288, a = r/16, p = r%16;
            float v = U0c[e];
            int o = (tap*288 + p*18 + a)*2;
            sUt2[o] = v; sUt2[o+1] = v;
        }
        for (int e = t; e < 2880; e += 576) {
            int tap = e/320, r = e%320, qq = r/20, d = r%20;
            sVp[e] = (d < 18) ? V0c[(tap*16 + qq)*18 + d] : 0.f;
        }
        for (int di = 0; di < 3; ++di) {
            const int hr = h - 1 + di;
            // stage one T row (previous readers finished at last tap's trailing sync)
            for (int e = t; e < 8192; e += 576) {
                int pq = e >> 5, w = e & 31;
                int p = pq >> 4, qq = pq & 15;
                sT1[(qq*16 + p)*33 + w] = ((unsigned)hr < 32u) ? xc[pq*1024 + hr*32 + w] : 0.f;
            }
            __syncthreads();
            for (int dj = 0; dj < 3; ++dj) {
                const int tap = di*3 + dj;
                const int iw = pixl + dj - 1;
                const bool valid = (unsigned)iw < 32u;
                if (valid && j < 16) {
                    const float* Tb = sT1 + iw;
                    u64 nacc[9];
                    #pragma unroll
                    for (int k = 0; k < 9; ++k) nacc[k] = 0ull;
                    #pragma unroll
                    for (int qq = 0; qq < 16; ++qq) {
                        u64 xd = dup2(Tb[(qq*16 + j)*33]);
                        FMA9(nacc, xd, sVp + tap*320 + qq*20);
                    }
                    ST9(sN + pixl*360 + j*20, nacc);
                }
                __syncthreads();
                if (valid) {
                    #pragma unroll
                    for (int p = 0; p < 16; ++p) {
                        u64 ud = *(const u64*)(sUt2 + (tap*288 + p*18 + j)*2);
                        FMA9(yacc, ud, sN + pixl*360 + p*20);
                    }
                }
                __syncthreads();
            }
        }
    }
    const int bid = b*32 + h;
    const size_t obase = ((size_t)bid*32 + pixl)*324 + j*18;
    #pragma unroll
    for (int k = 0; k < 9; ++k) *(u64*)(out + obase + 2*k) = yacc[k];
    ST9(sN + pixl*360 + j*20, yacc);
    __syncthreads();
    if (t < 324) {
        int a = t/18, d = t - a*18;
        float s = 0.f, ss = 0.f;
        #pragma unroll 4
        for (int pp = 0; pp < 32; ++pp) {
            float v = sN[pp*360 + a*20 + d];
            s += v; ss = fmaf(v, v, ss);
        }
        g_psum0[bid*324 + t] = s;
        g_psq0 [bid*324 + t] = ss;
    }
}

// ---------------- unified conv1x1 ----------------
// Input: BN+PReLU(inA) if inB==null, else bnA(inA)+bnB(inB). Outputs: out0 (req), out1 (opt).
__global__ void __launch_bounds__(576,2) conv1x1_kernel(
    const float* __restrict__ inA, int slotA,
    const float* __restrict__ inB, int slotB,
    const float* __restrict__ alpha_ptr,
    const float* __restrict__ U0w, const float* __restrict__ V0w,
    const float* __restrict__ b0w, float* __restrict__ out0,
    const float* __restrict__ U1w, const float* __restrict__ V1w,
    const float* __restrict__ b1w, float* __restrict__ out1)
{
    extern __shared__ float sm[];
    float* sV0  = sm;            // 360
    float* sV1  = sm + 360;      // 360
    float* sU0  = sm + 720;      // 648 dup
    float* sU1  = sm + 1368;     // 648 dup
    float* sB0  = sm + 2016;     // 360
    float* sB1  = sm + 2376;     // 360
    float* sScA = sm + 2736;     // 324
    float* sShA = sm + 3060;     // 324
    float* sScB = sm + 3384;     // 324
    float* sShB = sm + 3708;     // 324
    float* sXa  = sm + 4032;     // 11520
    float* sN   = sm + 15552;    // 11520
    const int t = threadIdx.x;
    const int j = t % 18, pixl = t / 18;
    const bool dual_in  = (inB  != nullptr);
    const bool dual_out = (out1 != nullptr);

    if (t < 360) {
        int q = t/20, d = t%20;
        sV0[t] = (d < 18) ? V0w[q*18 + d] : 0.f;
        sB0[t] = (d < 18) ? b0w[q*18 + d] : 0.f;
        if (dual_out) {
            sV1[t] = (d < 18) ? V1w[q*18 + d] : 0.f;
            sB1[t] = (d < 18) ? b1w[q*18 + d] : 0.f;
        }
    }
    for (int e = t; e < 324; e += 576) {
        float u = U0w[e];
        int o = ((e%18)*18 + e/18)*2;
        sU0[o] = u; sU0[o+1] = u;
        if (dual_out) { float u1 = U1w[e]; sU1[o] = u1; sU1[o+1] = u1; }
        sScA[e] = g_scale[slotA][e];
        sShA[e] = g_shift[slotA][e];
        if (dual_in) { sScB[e] = g_scale[slotB][e]; sShB[e] = g_shift[slotB][e]; }
    }
    const float alpha = (!dual_in && alpha_ptr) ? *alpha_ptr : 1.f;
    __syncthreads();

    const size_t base = ((size_t)blockIdx.x*32 + pixl)*324 + j*18;
    // activation -> sXa
    float* xa = sXa + pixl*360 + j*20;
    if (dual_in) {
        #pragma unroll
        for (int q = 0; q < 9; ++q) {
            float2 va  = *(const float2*)(inA + base + 2*q);
            float2 vb  = *(const float2*)(inB + base + 2*q);
            float2 scA = *(const float2*)(sScA + j*18 + 2*q);
            float2 shA = *(const float2*)(sShA + j*18 + 2*q);
            float2 scB = *(const float2*)(sScB + j*18 + 2*q);
            float2 shB = *(const float2*)(sShB + j*18 + 2*q);
            float a0 = fmaf(va.x, scA.x, shA.x) + fmaf(vb.x, scB.x, shB.x);
            float a1 = fmaf(va.y, scA.y, shA.y) + fmaf(vb.y, scB.y, shB.y);
            *(float2*)(xa + 2*q) = make_float2(a0, a1);
        }
    } else {
        #pragma unroll
        for (int q = 0; q < 9; ++q) {
            float2 v  = *(const float2*)(inA + base + 2*q);
            float2 sc = *(const float2*)(sScA + j*18 + 2*q);
            float2 sh = *(const float2*)(sShA + j*18 + 2*q);
            float a0 = fmaf(v.x, sc.x, sh.x); if (a0 < 0.f) a0 *= alpha;
            float a1 = fmaf(v.y, sc.y, sh.y); if (a1 < 0.f) a1 *= alpha;
            *(float2*)(xa + 2*q) = make_float2(a0, a1);
        }
    }
    __syncthreads();

    for (int pass = 0; pass < (dual_out ? 2 : 1); ++pass) {
        const float* sV  = pass ? sV1 : sV0;
        const float* sU  = pass ? sU1 : sU0;
        const float* sBp = pass ? sB1 : sB0;
        float* outp      = pass ? out1 : out0;
        float* psum      = pass ? g_psum1 : g_psum0;
        float* psq       = pass ? g_psq1  : g_psq0;

        u64 nacc[9];
        #pragma unroll
        for (int k = 0; k < 9; ++k) nacc[k] = 0ull;
        const float* xr = sXa + pixl*360 + j*20;
        #pragma unroll
        for (int q = 0; q < 18; ++q) {
            u64 xd = dup2(xr[q]);
            FMA9(nacc, xd, sV + q*20);
        }
        ST9(sN + pixl*360 + j*20, nacc);
        __syncthreads();

        u64 yacc[9];
        LD9BIAS(yacc, sBp + j*20);
        #pragma unroll
        for (int p = 0; p < 18; ++p) {
            u64 ud = *(const u64*)(sU + (p*18 + j)*2);
            FMA9(yacc, ud, sN + pixl*360 + p*20);
        }
        #pragma unroll
        for (int k = 0; k < 9; ++k) *(u64*)(outp + base + 2*k) = yacc[k];
        __syncthreads();
        ST9(sN + pixl*360 + j*20, yacc);
        __syncthreads();
        if (t < 324) {
            int a = t/18, d = t - a*18;
            float s = 0.f, ss = 0.f;
            #pragma unroll 4
            for (int pp = 0; pp < 32; ++pp) {
                float v = sN[pp*360 + a*20 + d];
                s += v; ss = fmaf(v, v, ss);
            }
            psum[blockIdx.x*324 + t] = s;
            psq [blockIdx.x*324 + t] = ss;
        }
        __syncthreads();
    }
}

// ---------------- conv3x3 (inline BN+PReLU on neighbor loads) ----------------
__global__ void __launch_bounds__(576,2) conv3x3_kernel(
    const float* __restrict__ in, int slot, const float* __restrict__ alpha_ptr,
    const float* __restrict__ U9, const float* __restrict__ V9,
    const float* __restrict__ bm, float* __restrict__ out)
{
    extern __shared__ float sm[];
    float* sV   = sm;            // 3240 [tap][q*20+d]
    float* sUt2 = sm + 3240;     // 5832 dup pairs [tap][(p*18+a)*2]
    float* sBp  = sm + 9072;     // 360
    float* sSc  = sm + 9432;     // 324
    float* sSh  = sm + 9756;     // 324
    float* sN   = sm + 10080;    // 11520  -> total 21600 w = 86400 B
    const int t = threadIdx.x;
    const int j = t % 18, pixl = t / 18;

    for (int e = t; e < 3240; e += 576) {
        int tap = e/360, r = e%360, q = r/20, d = r%20;
        sV[e] = (d < 18) ? V9[(tap*18 + q)*18 + d] : 0.f;
    }
    for (int e = t; e < 2916; e += 576) {
        int tap = e/324, r = e%324, a = r/18, p = r%18;
        float u = U9[e];
        int o = (tap*324 + p*18 + a)*2;
        sUt2[o] = u; sUt2[o+1] = u;
    }
    if (t < 360) { int q = t/20, d = t%20; sBp[t] = (d < 18) ? bm[q*18 + d] : 0.f; }
    for (int e = t; e < 324; e += 576) { sSc[e] = g_scale[slot][e]; sSh[e] = g_shift[slot][e]; }
    const float alpha = *alpha_ptr;
    __syncthreads();

    const int pix = blockIdx.x*32 + pixl;
    const int hw = pix & 1023, hh = hw >> 5, ww = hw & 31;
    u64 yacc[9];
    LD9BIAS(yacc, sBp + j*20);

    for (int tap = 0; tap < 9; ++tap) {
        const int di = tap/3 - 1, dj = tap%3 - 1;
        const bool valid = ((unsigned)(hh + di) < 32u) && ((unsigned)(ww + dj) < 32u);
        if (valid) {
            const float* xin = in + ((size_t)pix + di*32 + dj)*324 + j*18;
            u64 nacc[9];
            #pragma unroll
            for (int k = 0; k < 9; ++k) nacc[k] = 0ull;
            #pragma unroll
            for (int qp = 0; qp < 9; ++qp) {
                float2 v  = *(const float2*)(xin + 2*qp);
                float2 sc = *(const float2*)(sSc + j*18 + 2*qp);
                float2 sh = *(const float2*)(sSh + j*18 + 2*qp);
                float a0 = fmaf(v.x, sc.x, sh.x); if (a0 < 0.f) a0 *= alpha;
                float a1 = fmaf(v.y, sc.y, sh.y); if (a1 < 0.f) a1 *= alpha;
                u64 x0 = dup2(a0), x1 = dup2(a1);
                FMA9(nacc, x0, sV + tap*360 + (2*qp)*20);
                FMA9(nacc, x1, sV + tap*360 + (2*qp+1)*20);
            }
            ST9(sN + pixl*360 + j*20, nacc);
        }
        __syncthreads();
        if (valid) {
            #pragma unroll
            for (int p = 0; p < 18; ++p) {
                u64 ud = *(const u64*)(sUt2 + (tap*324 + p*18 + j)*2);
                FMA9(yacc, ud, sN + pixl*360 + p*20);
            }
        }
        __syncthreads();
    }
    const size_t base = (size_t)pix*324 + j*18;
    #pragma unroll
    for (int k = 0; k < 9; ++k) *(u64*)(out + base + 2*k) = yacc[k];
    ST9(sN + pixl*360 + j*20, yacc);
    __syncthreads();
    if (t < 324) {
        int a = t/18, d = t - a*18;
        float s = 0.f, ss = 0.f;
        #pragma unroll 4
        for (int pp = 0; pp < 32; ++pp) {
            float v = sN[pp*360 + a*20 + d];
            s += v; ss = fmaf(v, v, ss);
        }
        g_psum0[blockIdx.x*324 + t] = s;
        g_psq0 [blockIdx.x*324 + t] = ss;
    }
}

// ---------------- finalize ----------------
__global__ void __launch_bounds__(128) finalize_kernel(
    const float* __restrict__ psum, const float* __restrict__ psq,
    const float* __restrict__ gamma, const float* __restrict__ beta, int slot)
{
    __shared__ float red[8][128];
    const int t = threadIdx.x;
    const int bp = blockIdx.x * 4;
    float s0=0,s1=0,s2=0,s3=0,q0=0,q1=0,q2=0,q3=0;
    for (int i = t; i < NBLK; i += 128) {
        float4 a = *(const float4*)(psum + i*324 + bp);
        float4 b = *(const float4*)(psq  + i*324 + bp);
        s0+=a.x; s1+=a.y; s2+=a.z; s3+=a.w;
        q0+=b.x; q1+=b.y; q2+=b.z; q3+=b.w;
    }
    red[0][t]=s0; red[1][t]=s1; red[2][t]=s2; red[3][t]=s3;
    red[4][t]=q0; red[5][t]=q1; red[6][t]=q2; red[7][t]=q3;
    __syncthreads();
    for (int k = 64; k > 0; k >>= 1) {
        if (t < k) {
            #pragma unroll
            for (int c = 0; c < 8; ++c) red[c][t] += red[c][t+k];
        }
        __syncthreads();
    }
    if (t < 4) {
        const int pos = bp + t;
        float mean = red[t][0] * (1.f/32768.f);
        float var  = red[4+t][0] * (1.f/32768.f) - mean*mean;
        float inv  = rsqrtf(var + 1e-5f);
        float sc   = gamma[pos]*inv;
        g_scale[slot][pos] = sc;
        g_shift[slot][pos] = beta[pos] - mean*sc;
    }
}

// ---------------- head ----------------
__global__ void __launch_bounds__(324) head_kernel(
    const float* __restrict__ a, int slotA,
    const float* __restrict__ b, int slotB,
    const float* __restrict__ Wf, const float* __restrict__ bf,
    float* __restrict__ out) {
    __shared__ float sW[3240], sX[324], sPart[180];
    const int t = threadIdx.x;
    for (int e = t; e < 3240; e += 324) sW[e] = Wf[e];
    const float sA = g_scale[slotA][t], hA = g_shift[slotA][t];
    const float sB = g_scale[slotB][t], hB = g_shift[slotB][t];
    __syncthreads();
    const int pix0 = blockIdx.x * 8;
    for (int k = 0; k < 8; ++k) {
        const int pix = pix0 + k;
        const size_t base = (size_t)pix * 324;
        sX[t] = fmaf(a[base+t], sA, hA) + fmaf(b[base+t], sB, hB);
        __syncthreads();
        if (t < 180) {
            const int o = t/18, p = t - o*18;
            const float* xr = sX + p*18;
            const float* wr = sW + o*324 + p*18;
            float s = 0.f;
            #pragma unroll
            for (int q = 0; q < 18; ++q) s = fmaf(xr[q], wr[q], s);
            sPart[t] = s;
        }
        __syncthreads();
        if (t < 10) {
            float r = bf[t];
            #pragma unroll
            for (int p = 0; p < 18; ++p) r += sPart[t*18 + p];
            const int bb = pix >> 10, hw = pix & 1023;
            out[(size_t)(bb*10 + t)*1024 + hw] = r;
        }
        __syncthreads();
    }
}

// ---------------- host ----------------
extern "C" void kernel_launch(void* const* d_in, const int* in_sizes, int n_in,
                              void* d_out, int out_size) {
    (void)in_sizes; (void)n_in; (void)out_size;
    const float* x     = (const float*)d_in[0];
    const float* U0    = (const float*)d_in[1];
    const float* V0    = (const float*)d_in[2];
    const float* b0    = (const float*)d_in[3];
    const float* U1    = (const float*)d_in[4];
    const float* V1    = (const float*)d_in[5];
    const float* b1    = (const float*)d_in[6];
    const float* U3    = (const float*)d_in[7];
    const float* V3    = (const float*)d_in[8];
    const float* b3    = (const float*)d_in[9];
    const float* Wf    = (const float*)d_in[10];
    const float* bf    = (const float*)d_in[11];
    const float* gamma = (const float*)d_in[12];
    const float* beta  = (const float*)d_in[13];
    const float* alpha = (const float*)d_in[14];
    float* out = (float*)d_out;

    float *bufA, *bufB, *bufC, *bufD, *bufE;
    float *ps0, *pq0, *ps1, *pq1;
    cudaGetSymbolAddress((void**)&bufA, g_bufA);
    cudaGetSymbolAddress((void**)&bufB, g_bufB);
    cudaGetSymbolAddress((void**)&bufC, g_bufC);
    cudaGetSymbolAddress((void**)&bufD, g_bufD);
    cudaGetSymbolAddress((void**)&bufE, g_bufE);
    cudaGetSymbolAddress((void**)&ps0, g_psum0);
    cudaGetSymbolAddress((void**)&pq0, g_psq0);
    cudaGetSymbolAddress((void**)&ps1, g_psum1);
    cudaGetSymbolAddress((void**)&pq1, g_psq1);

    const int F0_SMEM = 28032 * 4;   // 112128 B
    const int C1_SMEM = 27072 * 4;   // 108288 B
    const int C3_SMEM = 21600 * 4;   //  86400 B
    cudaFuncSetAttribute(f0_kernel,      cudaFuncAttributeMaxDynamicSharedMemorySize, F0_SMEM);
    cudaFuncSetAttribute(conv1x1_kernel, cudaFuncAttributeMaxDynamicSharedMemorySize, C1_SMEM);
    cudaFuncSetAttribute(conv3x3_kernel, cudaFuncAttributeMaxDynamicSharedMemorySize, C3_SMEM);

    #define FIN0(slot, grow) finalize_kernel<<<81,128>>>(ps0, pq0, gamma + (grow)*324, beta + (grow)*324, (slot))
    #define FIN1(slot, grow) finalize_kernel<<<81,128>>>(ps1, pq1, gamma + (grow)*324, beta + (grow)*324, (slot))

    // f0 -> A (raw h), stats slot0 (gamma 0)
    f0_kernel<<<dim3(32,32), 576, F0_SMEM>>>(x, U0, V0, b0, bufA);
    FIN0(0, 0);

    // ---- block 1: dual-out (s1 -> B, t1 -> D) from prelu(bn(A,0)) ----
    conv1x1_kernel<<<1024,576,C1_SMEM>>>(bufA, 0, nullptr, 0, alpha+0,
        U1+0*324, V1+0*324, b1+0*324, bufB,
        U1+1*324, V1+1*324, b1+1*324, bufD);
    FIN0(1, 1); FIN1(2, 2);
    conv3x3_kernel<<<1024,576,C3_SMEM>>>(bufD, 2, alpha+1, U3+0*2916, V3+0*2916, b3+0*324, bufE);
    FIN0(3, 3);
    conv1x1_kernel<<<1024,576,C1_SMEM>>>(bufE, 3, nullptr, 0, alpha+2,
        U1+2*324, V1+2*324, b1+2*324, bufD,
        nullptr, nullptr, nullptr, nullptr);
    FIN0(4, 4);

    // ---- block 2: input x11 = bn(D,4)+bn(B,1); dual-out (s2 -> C, t1 -> A) ----
    conv1x1_kernel<<<1024,576,C1_SMEM>>>(bufD, 4, bufB, 1, nullptr,
        U1+3*324, V1+3*324, b1+3*324, bufC,
        U1+4*324, V1+4*324, b1+4*324, bufA);
    FIN0(5, 5); FIN1(6, 6);
    conv3x3_kernel<<<1024,576,C3_SMEM>>>(bufA, 6, alpha+3, U3+1*2916, V3+1*2916, b3+1*324, bufE);
    FIN0(7, 7);
    conv1x1_kernel<<<1024,576,C1_SMEM>>>(bufE, 7, nullptr, 0, alpha+4,
        U1+5*324, V1+5*324, b1+5*324, bufD,
        nullptr, nullptr, nullptr, nullptr);
    FIN0(8, 8);

    // ---- block 3: input x21 = bn(D,8)+bn(C,5); single-out t1 -> A
    //      (bug-faithful: identity = bn(s2); U1[6]/gamma[9] conv unused) ----
    conv1x1_kernel<<<1024,576,C1_SMEM>>>(bufD, 8, bufC, 5, nullptr,
        U1+7*324, V1+7*324, b1+7*324, bufA,
        nullptr, nullptr, nullptr, nullptr);
    FIN0(9, 10);
    conv3x3_kernel<<<1024,576,C3_SMEM>>>(bufA, 9, alpha+5, U3+2*2916, V3+2*2916, b3+2*324, bufE);
    FIN0(10, 11);
    conv1x1_kernel<<<1024,576,C1_SMEM>>>(bufE, 10, nullptr, 0, alpha+6,
        U1+8*324, V1+8*324, b1+8*324, bufD,
        nullptr, nullptr, nullptr, nullptr);
    FIN0(11, 12);

    // head: out = <bn(t3,11) + bn(s2,5), Wf> + bf
    head_kernel<<<4096,324>>>(bufD, 11, bufC, 5, Wf, bf, out);
}

// round 6
// speedup vs baseline: 1.1664x; 1.0095x over previous
#include <cuda_runtime.h>
#include <cstdint>

typedef unsigned long long u64;

#define NPIX 32768
#define NBLK 1024

// ---------------- scratch ----------------
__device__ float g_bufA[NPIX*324];
__device__ float g_bufB[NPIX*324];
__device__ float g_bufC[NPIX*324];
__device__ float g_bufD[NPIX*324];
__device__ float g_bufE[NPIX*324];

// transposed partials: [pos][blk]
__device__ float g_psum0[324*NBLK];
__device__ float g_psq0 [324*NBLK];
__device__ float g_psum1[324*NBLK];
__device__ float g_psq1 [324*NBLK];
__device__ float g_scale[12][324];
__device__ float g_shift[12][324];

// ---------------- f32x2 helpers ----------------
__device__ __forceinline__ u64 pk2(float lo, float hi){ u64 r; asm("mov.b64 %0,{%1,%2};":"=l"(r):"f"(lo),"f"(hi)); return r; }
__device__ __forceinline__ u64 dup2(float v){ return pk2(v, v); }
__device__ __forceinline__ void fma2(u64 &d, u64 a, u64 b){ asm("fma.rn.f32x2 %0,%1,%2,%0;":"+l"(d):"l"(a),"l"(b)); }

#define FMA9(acc, xd, vbase) { \
  const ulonglong2* _vv = (const ulonglong2*)(vbase); \
  ulonglong2 _a0=_vv[0], _a1=_vv[1], _a2=_vv[2], _a3=_vv[3]; \
  u64 _a8 = ((const u64*)(vbase))[8]; \
  fma2(acc[0],xd,_a0.x); fma2(acc[1],xd,_a0.y); \
  fma2(acc[2],xd,_a1.x); fma2(acc[3],xd,_a1.y); \
  fma2(acc[4],xd,_a2.x); fma2(acc[5],xd,_a2.y); \
  fma2(acc[6],xd,_a3.x); fma2(acc[7],xd,_a3.y); \
  fma2(acc[8],xd,_a8); }

#define ST9(dst, acc) { \
  ulonglong2* _dd=(ulonglong2*)(dst); \
  _dd[0]=make_ulonglong2(acc[0],acc[1]); _dd[1]=make_ulonglong2(acc[2],acc[3]); \
  _dd[2]=make_ulonglong2(acc[4],acc[5]); _dd[3]=make_ulonglong2(acc[6],acc[7]); \
  ((u64*)(dst))[8]=acc[8]; }

#define LD9BIAS(yacc, bptr) { \
  const ulonglong2* _bb = (const ulonglong2*)(bptr); \
  ulonglong2 _b0=_bb[0], _b1=_bb[1], _b2=_bb[2], _b3=_bb[3]; \
  yacc[0]=_b0.x; yacc[1]=_b0.y; yacc[2]=_b1.x; yacc[3]=_b1.y; \
  yacc[4]=_b2.x; yacc[5]=_b2.y; yacc[6]=_b3.x; yacc[7]=_b3.y; \
  yacc[8]=((const u64*)(bptr))[8]; }

// ---------------- dummy (profiler alignment: puts f0 at launch #4) ----------------
__global__ void dummy_kernel() {}

// ---------------- f0 ----------------
__global__ void __launch_bounds__(576,2) f0_kernel(const float* __restrict__ x,
    const float* __restrict__ U0, const float* __restrict__ V0,
    const float* __restrict__ b0, float* __restrict__ out)
{
    extern __shared__ float sm[];
    float* sT1  = sm;             // 8448
    float* sUt2 = sm + 8448;      // 5184 dup pairs [tap][(p*18+a)*2]
    float* sVp  = sm + 13632;     // 2880 [tap][qq*20+d]
    float* sN   = sm + 16512;     // 11520
    const int t = threadIdx.x;
    const int j = t % 18, pixl = t / 18;
    const int h = blockIdx.x, b = blockIdx.y;

    u64 yacc[9];
    #pragma unroll
    for (int k = 0; k < 9; ++k) yacc[k] = *(const u64*)(b0 + j*18 + 2*k);

    for (int c = 0; c < 8; ++c) {
        const float* xc  = x  + (size_t)(b*8 + c)*262144;
        const float* U0c = U0 + c*2592;   // [tap][a][p]
        const float* V0c = V0 + c*2592;   // [tap][qq][d]
        for (int e = t; e < 2592; e += 576) {
            int tap = e/288, r = e%288, a = r/16, p = r%16;
            float v = U0c[e];
            int o = (tap*288 + p*18 + a)*2;
            sUt2[o] = v; sUt2[o+1] = v;
        }
        for (int e = t; e < 2880; e += 576) {
            int tap = e/320, r = e%320, qq = r/20, d = r%20;
            sVp[e] = (d < 18) ? V0c[(tap*16 + qq)*18 + d] : 0.f;
        }
        for (int di = 0; di < 3; ++di) {
            const int hr = h - 1 + di;
            for (int e = t; e < 8192; e += 576) {
                int pq = e >> 5, w = e & 31;
                int p = pq >> 4, qq = pq & 15;
                sT1[(qq*16 + p)*33 + w] = ((unsigned)hr < 32u) ? xc[pq*1024 + hr*32 + w] : 0.f;
            }
            __syncthreads();
            for (int dj = 0; dj < 3; ++dj) {
                const int tap = di*3 + dj;
                const int iw = pixl + dj - 1;
                const bool valid = (unsigned)iw < 32u;
                if (valid && j < 16) {
                    const float* Tb = sT1 + iw;
                    u64 nacc[9];
                    #pragma unroll
                    for (int k = 0; k < 9; ++k) nacc[k] = 0ull;
                    #pragma unroll
                    for (int qq = 0; qq < 16; ++qq) {
                        u64 xd = dup2(Tb[(qq*16 + j)*33]);
                        FMA9(nacc, xd, sVp + tap*320 + qq*20);
                    }
                    ST9(sN + pixl*360 + j*20, nacc);
                }
                __syncthreads();
                if (valid) {
                    #pragma unroll
                    for (int p = 0; p < 16; ++p) {
                        u64 ud = *(const u64*)(sUt2 + (tap*288 + p*18 + j)*2);
                        FMA9(yacc, ud, sN + pixl*360 + p*20);
                    }
                }
                __syncthreads();
            }
        }
    }
    const int bid = b*32 + h;
    const size_t obase = ((size_t)bid*32 + pixl)*324 + j*18;
    #pragma unroll
    for (int k = 0; k < 9; ++k) *(u64*)(out + obase + 2*k) = yacc[k];
    ST9(sN + pixl*360 + j*20, yacc);
    __syncthreads();
    if (t < 324) {
        int a = t/18, d = t - a*18;
        float s = 0.f, ss = 0.f;
        #pragma unroll 4
        for (int pp = 0; pp < 32; ++pp) {
            float v = sN[pp*360 + a*20 + d];
            s += v; ss = fmaf(v, v, ss);
        }
        g_psum0[t*NBLK + bid] = s;
        g_psq0 [t*NBLK + bid] = ss;
    }
}

// ---------------- unified conv1x1 ----------------
__global__ void __launch_bounds__(576,2) conv1x1_kernel(
    const float* __restrict__ inA, int slotA,
    const float* __restrict__ inB, int slotB,
    const float* __restrict__ alpha_ptr,
    const float* __restrict__ U0w, const float* __restrict__ V0w,
    const float* __restrict__ b0w, float* __restrict__ out0,
    const float* __restrict__ U1w, const float* __restrict__ V1w,
    const float* __restrict__ b1w, float* __restrict__ out1)
{
    extern __shared__ float sm[];
    float* sV0  = sm;            // 360
    float* sV1  = sm + 360;      // 360
    float* sU0  = sm + 720;      // 648 dup
    float* sU1  = sm + 1368;     // 648 dup
    float* sB0  = sm + 2016;     // 360
    float* sB1  = sm + 2376;     // 360
    float* sScA = sm + 2736;     // 324
    float* sShA = sm + 3060;     // 324
    float* sScB = sm + 3384;     // 324
    float* sShB = sm + 3708;     // 324
    float* sXa  = sm + 4032;     // 11520
    float* sN   = sm + 15552;    // 11520
    const int t = threadIdx.x;
    const int j = t % 18, pixl = t / 18;
    const bool dual_in  = (inB  != nullptr);
    const bool dual_out = (out1 != nullptr);

    if (t < 360) {
        int q = t/20, d = t%20;
        sV0[t] = (d < 18) ? V0w[q*18 + d] : 0.f;
        sB0[t] = (d < 18) ? b0w[q*18 + d] : 0.f;
        if (dual_out) {
            sV1[t] = (d < 18) ? V1w[q*18 + d] : 0.f;
            sB1[t] = (d < 18) ? b1w[q*18 + d] : 0.f;
        }
    }
    for (int e = t; e < 324; e += 576) {
        float u = U0w[e];
        int o = ((e%18)*18 + e/18)*2;
        sU0[o] = u; sU0[o+1] = u;
        if (dual_out) { float u1 = U1w[e]; sU1[o] = u1; sU1[o+1] = u1; }
        sScA[e] = g_scale[slotA][e];
        sShA[e] = g_shift[slotA][e];
        if (dual_in) { sScB[e] = g_scale[slotB][e]; sShB[e] = g_shift[slotB][e]; }
    }
    const float alpha = (!dual_in && alpha_ptr) ? *alpha_ptr : 1.f;
    __syncthreads();

    const size_t base = ((size_t)blockIdx.x*32 + pixl)*324 + j*18;
    float* xa = sXa + pixl*360 + j*20;
    if (dual_in) {
        #pragma unroll
        for (int q = 0; q < 9; ++q) {
            float2 va  = *(const float2*)(inA + base + 2*q);
            float2 vb  = *(const float2*)(inB + base + 2*q);
            float2 scA = *(const float2*)(sScA + j*18 + 2*q);
            float2 shA = *(const float2*)(sShA + j*18 + 2*q);
            float2 scB = *(const float2*)(sScB + j*18 + 2*q);
            float2 shB = *(const float2*)(sShB + j*18 + 2*q);
            float a0 = fmaf(va.x, scA.x, shA.x) + fmaf(vb.x, scB.x, shB.x);
            float a1 = fmaf(va.y, scA.y, shA.y) + fmaf(vb.y, scB.y, shB.y);
            *(float2*)(xa + 2*q) = make_float2(a0, a1);
        }
    } else {
        #pragma unroll
        for (int q = 0; q < 9; ++q) {
            float2 v  = *(const float2*)(inA + base + 2*q);
            float2 sc = *(const float2*)(sScA + j*18 + 2*q);
            float2 sh = *(const float2*)(sShA + j*18 + 2*q);
            float a0 = fmaf(v.x, sc.x, sh.x); if (a0 < 0.f) a0 *= alpha;
            float a1 = fmaf(v.y, sc.y, sh.y); if (a1 < 0.f) a1 *= alpha;
            *(float2*)(xa + 2*q) = make_float2(a0, a1);
        }
    }
    __syncthreads();

    for (int pass = 0; pass < (dual_out ? 2 : 1); ++pass) {
        const float* sV  = pass ? sV1 : sV0;
        const float* sU  = pass ? sU1 : sU0;
        const float* sBp = pass ? sB1 : sB0;
        float* outp      = pass ? out1 : out0;
        float* psum      = pass ? g_psum1 : g_psum0;
        float* psq       = pass ? g_psq1  : g_psq0;

        u64 nacc[9];
        #pragma unroll
        for (int k = 0; k < 9; ++k) nacc[k] = 0ull;
        const float* xr = sXa + pixl*360 + j*20;
        #pragma unroll
        for (int q = 0; q < 18; ++q) {
            u64 xd = dup2(xr[q]);
            FMA9(nacc, xd, sV + q*20);
        }
        ST9(sN + pixl*360 + j*20, nacc);
        __syncthreads();

        u64 yacc[9];
        LD9BIAS(yacc, sBp + j*20);
        #pragma unroll
        for (int p = 0; p < 18; ++p) {
            u64 ud = *(const u64*)(sU + (p*18 + j)*2);
            FMA9(yacc, ud, sN + pixl*360 + p*20);
        }
        #pragma unroll
        for (int k = 0; k < 9; ++k) *(u64*)(outp + base + 2*k) = yacc[k];
        __syncthreads();
        ST9(sN + pixl*360 + j*20, yacc);
        __syncthreads();
        if (t < 324) {
            int a = t/18, d = t - a*18;
            float s = 0.f, ss = 0.f;
            #pragma unroll 4
            for (int pp = 0; pp < 32; ++pp) {
                float v = sN[pp*360 + a*20 + d];
                s += v; ss = fmaf(v, v, ss);
            }
            psum[t*NBLK + blockIdx.x] = s;
            psq [t*NBLK + blockIdx.x] = ss;
        }
        __syncthreads();
    }
}

// ---------------- conv3x3 ----------------
__global__ void __launch_bounds__(576,2) conv3x3_kernel(
    const float* __restrict__ in, int slot, const float* __restrict__ alpha_ptr,
    const float* __restrict__ U9, const float* __restrict__ V9,
    const float* __restrict__ bm, float* __restrict__ out)
{
    extern __shared__ float sm[];
    float* sV   = sm;            // 3240
    float* sUt2 = sm + 3240;     // 5832
    float* sBp  = sm + 9072;     // 360
    float* sSc  = sm + 9432;     // 324
    float* sSh  = sm + 9756;     // 324
    float* sN   = sm + 10080;    // 11520
    const int t = threadIdx.x;
    const int j = t % 18, pixl = t / 18;

    for (int e = t; e < 3240; e += 576) {
        int tap = e/360, r = e%360, q = r/20, d = r%20;
        sV[e] = (d < 18) ? V9[(tap*18 + q)*18 + d] : 0.f;
    }
    for (int e = t; e < 2916; e += 576) {
        int tap = e/324, r = e%324, a = r/18, p = r%18;
        float u = U9[e];
        int o = (tap*324 + p*18 + a)*2;
        sUt2[o] = u; sUt2[o+1] = u;
    }
    if (t < 360) { int q = t/20, d = t%20; sBp[t] = (d < 18) ? bm[q*18 + d] : 0.f; }
    for (int e = t; e < 324; e += 576) { sSc[e] = g_scale[slot][e]; sSh[e] = g_shift[slot][e]; }
    const float alpha = *alpha_ptr;
    __syncthreads();

    const int pix = blockIdx.x*32 + pixl;
    const int hw = pix & 1023, hh = hw >> 5, ww = hw & 31;
    u64 yacc[9];
    LD9BIAS(yacc, sBp + j*20);

    for (int tap = 0; tap < 9; ++tap) {
        const int di = tap/3 - 1, dj = tap%3 - 1;
        const bool valid = ((unsigned)(hh + di) < 32u) && ((unsigned)(ww + dj) < 32u);
        if (valid) {
            const float* xin = in + ((size_t)pix + di*32 + dj)*324 + j*18;
            u64 nacc[9];
            #pragma unroll
            for (int k = 0; k < 9; ++k) nacc[k] = 0ull;
            #pragma unroll
            for (int qp = 0; qp < 9; ++qp) {
                float2 v  = *(const float2*)(xin + 2*qp);
                float2 sc = *(const float2*)(sSc + j*18 + 2*qp);
                float2 sh = *(const float2*)(sSh + j*18 + 2*qp);
                float a0 = fmaf(v.x, sc.x, sh.x); if (a0 < 0.f) a0 *= alpha;
                float a1 = fmaf(v.y, sc.y, sh.y); if (a1 < 0.f) a1 *= alpha;
                u64 x0 = dup2(a0), x1 = dup2(a1);
                FMA9(nacc, x0, sV + tap*360 + (2*qp)*20);
                FMA9(nacc, x1, sV + tap*360 + (2*qp+1)*20);
            }
            ST9(sN + pixl*360 + j*20, nacc);
        }
        __syncthreads();
        if (valid) {
            #pragma unroll
            for (int p = 0; p < 18; ++p) {
                u64 ud = *(const u64*)(sUt2 + (tap*324 + p*18 + j)*2);
                FMA9(yacc, ud, sN + pixl*360 + p*20);
            }
        }
        __syncthreads();
    }
    const size_t base = (size_t)pix*324 + j*18;
    #pragma unroll
    for (int k = 0; k < 9; ++k) *(u64*)(out + base + 2*k) = yacc[k];
    ST9(sN + pixl*360 + j*20, yacc);
    __syncthreads();
    if (t < 324) {
        int a = t/18, d = t - a*18;
        float s = 0.f, ss = 0.f;
        #pragma unroll 4
        for (int pp = 0; pp < 32; ++pp) {
            float v = sN[pp*360 + a*20 + d];
            s += v; ss = fmaf(v, v, ss);
        }
        g_psum0[t*NBLK + blockIdx.x] = s;
        g_psq0 [t*NBLK + blockIdx.x] = ss;
    }
}

// ---------------- finalize: coalesced float4 + warp shuffle ----------------
// grid 324 (one block per inner position), 256 threads.
__global__ void __launch_bounds__(256) finalize_kernel(
    const float* __restrict__ psum, const float* __restrict__ psq,
    const float* __restrict__ gamma, const float* __restrict__ beta, int slot)
{
    const int pos = blockIdx.x, t = threadIdx.x;
    float4 a = ((const float4*)(psum + pos*NBLK))[t];
    float4 b = ((const float4*)(psq  + pos*NBLK))[t];
    float s  = (a.x + a.y) + (a.z + a.w);
    float ss = (b.x + b.y) + (b.z + b.w);
    #pragma unroll
    for (int o = 16; o > 0; o >>= 1) {
        s  += __shfl_down_sync(0xffffffffu, s,  o);
        ss += __shfl_down_sync(0xffffffffu, ss, o);
    }
    __shared__ float rs[8], rq[8];
    if ((t & 31) == 0) { rs[t>>5] = s; rq[t>>5] = ss; }
    __syncthreads();
    if (t == 0) {
        s = 0.f; ss = 0.f;
        #pragma unroll
        for (int i = 0; i < 8; ++i) { s += rs[i]; ss += rq[i]; }
        float mean = s * (1.f/32768.f);
        float var  = ss * (1.f/32768.f) - mean*mean;
        float inv  = rsqrtf(var + 1e-5f);
        float sc   = gamma[pos]*inv;
        g_scale[slot][pos] = sc;
        g_shift[slot][pos] = beta[pos] - mean*sc;
    }
}

// ---------------- head ----------------
__global__ void __launch_bounds__(324) head_kernel(
    const float* __restrict__ a, int slotA,
    const float* __restrict__ b, int slotB,
    const float* __restrict__ Wf, const float* __restrict__ bf,
    float* __restrict__ out) {
    __shared__ float sW[3240], sX[324], sPart[180];
    const int t = threadIdx.x;
    for (int e = t; e < 3240; e += 324) sW[e] = Wf[e];
    const float sA = g_scale[slotA][t], hA = g_shift[slotA][t];
    const float sB = g_scale[slotB][t], hB = g_shift[slotB][t];
    __syncthreads();
    const int pix0 = blockIdx.x * 8;
    for (int k = 0; k < 8; ++k) {
        const int pix = pix0 + k;
        const size_t base = (size_t)pix * 324;
        sX[t] = fmaf(a[base+t], sA, hA) + fmaf(b[base+t], sB, hB);
        __syncthreads();
        if (t < 180) {
            const int o = t/18, p = t - o*18;
            const float* xr = sX + p*18;
            const float* wr = sW + o*324 + p*18;
            float s = 0.f;
            #pragma unroll
            for (int q = 0; q < 18; ++q) s = fmaf(xr[q], wr[q], s);
            sPart[t] = s;
        }
        __syncthreads();
        if (t < 10) {
            float r = bf[t];
            #pragma unroll
            for (int p = 0; p < 18; ++p) r += sPart[t*18 + p];
            const int bb = pix >> 10, hw = pix & 1023;
            out[(size_t)(bb*10 + t)*1024 + hw] = r;
        }
        __syncthreads();
    }
}

// ---------------- host ----------------
extern "C" void kernel_launch(void* const* d_in, const int* in_sizes, int n_in,
                              void* d_out, int out_size) {
    (void)in_sizes; (void)n_in; (void)out_size;
    const float* x     = (const float*)d_in[0];
    const float* U0    = (const float*)d_in[1];
    const float* V0    = (const float*)d_in[2];
    const float* b0    = (const float*)d_in[3];
    const float* U1    = (const float*)d_in[4];
    const float* V1    = (const float*)d_in[5];
    const float* b1    = (const float*)d_in[6];
    const float* U3    = (const float*)d_in[7];
    const float* V3    = (const float*)d_in[8];
    const float* b3    = (const float*)d_in[9];
    const float* Wf    = (const float*)d_in[10];
    const float* bf    = (const float*)d_in[11];
    const float* gamma = (const float*)d_in[12];
    const float* beta  = (const float*)d_in[13];
    const float* alpha = (const float*)d_in[14];
    float* out = (float*)d_out;

    float *bufA, *bufB, *bufC, *bufD, *bufE;
    float *ps0, *pq0, *ps1, *pq1;
    cudaGetSymbolAddress((void**)&bufA, g_bufA);
    cudaGetSymbolAddress((void**)&bufB, g_bufB);
    cudaGetSymbolAddress((void**)&bufC, g_bufC);
    cudaGetSymbolAddress((void**)&bufD, g_bufD);
    cudaGetSymbolAddress((void**)&bufE, g_bufE);
    cudaGetSymbolAddress((void**)&ps0, g_psum0);
    cudaGetSymbolAddress((void**)&pq0, g_psq0);
    cudaGetSymbolAddress((void**)&ps1, g_psum1);
    cudaGetSymbolAddress((void**)&pq1, g_psq1);

    const int F0_SMEM = 28032 * 4;
    const int C1_SMEM = 27072 * 4;
    const int C3_SMEM = 21600 * 4;
    cudaFuncSetAttribute(f0_kernel,      cudaFuncAttributeMaxDynamicSharedMemorySize, F0_SMEM);
    cudaFuncSetAttribute(conv1x1_kernel, cudaFuncAttributeMaxDynamicSharedMemorySize, C1_SMEM);
    cudaFuncSetAttribute(conv3x3_kernel, cudaFuncAttributeMaxDynamicSharedMemorySize, C3_SMEM);

    #define FIN0(slot, grow) finalize_kernel<<<324,256>>>(ps0, pq0, gamma + (grow)*324, beta + (grow)*324, (slot))
    #define FIN1(slot, grow) finalize_kernel<<<324,256>>>(ps1, pq1, gamma + (grow)*324, beta + (grow)*324, (slot))

    // profiler alignment: ncu captures launch #4 -> make it f0
    dummy_kernel<<<1,32>>>();
    dummy_kernel<<<1,32>>>();
    dummy_kernel<<<1,32>>>();

    // f0 -> A (raw h), stats slot0 (gamma 0)
    f0_kernel<<<dim3(32,32), 576, F0_SMEM>>>(x, U0, V0, b0, bufA);
    FIN0(0, 0);

    // ---- block 1: dual-out (s1 -> B, t1 -> D) from prelu(bn(A,0)) ----
    conv1x1_kernel<<<1024,576,C1_SMEM>>>(bufA, 0, nullptr, 0, alpha+0,
        U1+0*324, V1+0*324, b1+0*324, bufB,
        U1+1*324, V1+1*324, b1+1*324, bufD);
    FIN0(1, 1); FIN1(2, 2);
    conv3x3_kernel<<<1024,576,C3_SMEM>>>(bufD, 2, alpha+1, U3+0*2916, V3+0*2916, b3+0*324, bufE);
    FIN0(3, 3);
    conv1x1_kernel<<<1024,576,C1_SMEM>>>(bufE, 3, nullptr, 0, alpha+2,
        U1+2*324, V1+2*324, b1+2*324, bufD,
        nullptr, nullptr, nullptr, nullptr);
    FIN0(4, 4);

    // ---- block 2: input x11 = bn(D,4)+bn(B,1); dual-out (s2 -> C, t1 -> A) ----
    conv1x1_kernel<<<1024,576,C1_SMEM>>>(bufD, 4, bufB, 1, nullptr,
        U1+3*324, V1+3*324, b1+3*324, bufC,
        U1+4*324, V1+4*324, b1+4*324, bufA);
    FIN0(5, 5); FIN1(6, 6);
    conv3x3_kernel<<<1024,576,C3_SMEM>>>(bufA, 6, alpha+3, U3+1*2916, V3+1*2916, b3+1*324, bufE);
    FIN0(7, 7);
    conv1x1_kernel<<<1024,576,C1_SMEM>>>(bufE, 7, nullptr, 0, alpha+4,
        U1+5*324, V1+5*324, b1+5*324, bufD,
        nullptr, nullptr, nullptr, nullptr);
    FIN0(8, 8);

    // ---- block 3: input x21 = bn(D,8)+bn(C,5); single-out t1 -> A
    //      (bug-faithful: identity = bn(s2); U1[6]/gamma[9] conv unused) ----
    conv1x1_kernel<<<1024,576,C1_SMEM>>>(bufD, 8, bufC, 5, nullptr,
        U1+7*324, V1+7*324, b1+7*324, bufA,
        nullptr, nullptr, nullptr, nullptr);
    FIN0(9, 10);
    conv3x3_kernel<<<1024,576,C3_SMEM>>>(bufA, 9, alpha+5, U3+2*2916, V3+2*2916, b3+2*324, bufE);
    FIN0(10, 11);
    conv1x1_kernel<<<1024,576,C1_SMEM>>>(bufE, 10, nullptr, 0, alpha+6,
        U1+8*324, V1+8*324, b1+8*324, bufD,
        nullptr, nullptr, nullptr, nullptr);
    FIN0(11, 12);

    // head: out = <bn(t3,11) + bn(s2,5), Wf> + bf
    head_kernel<<<4096,324>>>(bufD, 11, bufC, 5, Wf, bf, out);
}